// round 6
// baseline (speedup 1.0000x reference)
#include <cuda_runtime.h>
#include <cuda_bf16.h>
#include <math.h>

// Problem constants
#define SD 128      // STATE_DIM
#define NH 32       // HIDDEN
#define BATCH 512
#define ROWS 4      // batch rows per block
#define THREADS 512 // 16 warps, role-partitioned

// Math identity (verified R1-R5, rel_err ~9e-8):
//   out[b,n] = exp(log_amp[n,month]) *
//     softplus( sum_h relu(x[b]@W1 + emb*W1[128,:] + b1)[h] * mean_n W2[h,n] + mean(b2) )
//
// Warp roles (producer/consumer split via named barrier 0):
//   warps 0-3  : matvec producers; warp c = input chunk c for ALL 4 rows
//   warps 4-7  : W2 row-mean producers (8 rows each, coalesced float4)
//   warps 8-11 : amp-table producers (exp(log_amp[:,month]))
//   warps 12-15: consumers/finishers (warp 12 also produces b2 mean)
//   producers bar.arrive and exit; consumers bar.sync.

__global__ __launch_bounds__(THREADS, 1) void gnm_kernel(
    const float* __restrict__ x,        // [512,128]
    const float* __restrict__ t,        // [1]
    const float* __restrict__ log_amp,  // [128,12]
    const float* __restrict__ W1,       // [129,32]
    const float* __restrict__ b1,       // [32]
    const float* __restrict__ W2,       // [32,128]
    const float* __restrict__ b2,       // [128]
    float* __restrict__ out)            // [512,128]
{
    __shared__ float  s_part[4 * ROWS * NH];   // [chunk][row][h]
    __shared__ float  s_w2m[NH];               // W2 row means
    __shared__ float  s_amp[SD];
    __shared__ float  s_b2m;
    __shared__ float4 s_xt[4][NH];             // [chunk][j] = (x_row0..x_row3)[j]

    const int tid  = threadIdx.x;
    const int lane = tid & 31;
    const int warp = tid >> 5;
    const int b0   = blockIdx.x * ROWS;

    const float tv = t[0];

    if (warp < 4) {
        // ---------------- matvec: warp c handles chunk c for 4 rows ----------------
        const int c = warp;
        const float xv0 = x[(b0 + 0) * SD + c * 32 + lane];
        const float xv1 = x[(b0 + 1) * SD + c * 32 + lane];
        const float xv2 = x[(b0 + 2) * SD + c * 32 + lane];
        const float xv3 = x[(b0 + 3) * SD + c * 32 + lane];

        // Explicit W1 batch: 32 coalesced LDGs issued back-to-back (one MLP window)
        const float* __restrict__ w1p = W1 + (c * 32) * NH + lane;
        float w[32];
        #pragma unroll
        for (int j = 0; j < 32; j++) w[j] = w1p[j * NH];

        s_xt[c][lane] = make_float4(xv0, xv1, xv2, xv3);   // conflict-free STS.128
        __syncwarp();

        float p0a = 0.f, p1a = 0.f, p2a = 0.f, p3a = 0.f;
        float p0b = 0.f, p1b = 0.f, p2b = 0.f, p3b = 0.f;
        #pragma unroll
        for (int j = 0; j < 32; j += 2) {
            const float4 xa = s_xt[c][j + 0];      // LDS.128 broadcast
            const float4 xb = s_xt[c][j + 1];
            p0a = fmaf(xa.x, w[j],     p0a); p1a = fmaf(xa.y, w[j],     p1a);
            p2a = fmaf(xa.z, w[j],     p2a); p3a = fmaf(xa.w, w[j],     p3a);
            p0b = fmaf(xb.x, w[j + 1], p0b); p1b = fmaf(xb.y, w[j + 1], p1b);
            p2b = fmaf(xb.z, w[j + 1], p2b); p3b = fmaf(xb.w, w[j + 1], p3b);
        }
        s_part[c * (ROWS * NH) + 0 * NH + lane] = p0a + p0b;
        s_part[c * (ROWS * NH) + 1 * NH + lane] = p1a + p1b;
        s_part[c * (ROWS * NH) + 2 * NH + lane] = p2a + p2b;
        s_part[c * (ROWS * NH) + 3 * NH + lane] = p3a + p3b;
        asm volatile("bar.arrive 0, %0;" :: "n"(THREADS));
        return;
    }

    if (warp < 8) {
        // ---------------- W2 row means: warp g, rows g*8 .. g*8+7 ----------------
        const int g = warp - 4;
        #pragma unroll
        for (int i = 0; i < 8; i++) {
            const int   r = g * 8 + i;
            const float4 v = reinterpret_cast<const float4*>(W2 + r * SD)[lane];
            float s = (v.x + v.y) + (v.z + v.w);
            #pragma unroll
            for (int off = 16; off; off >>= 1)
                s += __shfl_xor_sync(0xffffffffu, s, off);
            if (lane == 0) s_w2m[r] = s * (1.0f / SD);
        }
        asm volatile("bar.arrive 0, %0;" :: "n"(THREADS));
        return;
    }

    if (warp < 12) {
        // ---------------- amp table: thread n = tid-256 in 0..127 ----------------
        const int n = tid - 256;
        const float4* lar = reinterpret_cast<const float4*>(log_amp + n * 12);
        const float4 la0 = lar[0], la1 = lar[1], la2 = lar[2];
        const float tm = (tv >= 12.0f) ? (tv - 12.0f) : tv;   // t in [0,24)
        const int month = (int)tm;
        float la = la0.x;
        la = (month ==  1) ? la0.y : la;
        la = (month ==  2) ? la0.z : la;
        la = (month ==  3) ? la0.w : la;
        la = (month ==  4) ? la1.x : la;
        la = (month ==  5) ? la1.y : la;
        la = (month ==  6) ? la1.z : la;
        la = (month ==  7) ? la1.w : la;
        la = (month ==  8) ? la2.x : la;
        la = (month ==  9) ? la2.y : la;
        la = (month == 10) ? la2.z : la;
        la = (month == 11) ? la2.w : la;
        s_amp[n] = __expf(la);
        asm volatile("bar.arrive 0, %0;" :: "n"(THREADS));
        return;
    }

    // ---------------- consumers: prefetch, then bar.sync ----------------
    const float b1v = b1[lane];
    const float w1e = W1[SD * NH + lane];
    const float emb = __sinf(0.5235987755982988f * tv);   // sin(2*pi*t/12)
    if (warp == 12) {
        const float4 bv = reinterpret_cast<const float4*>(b2)[lane];
        float s = (bv.x + bv.y) + (bv.z + bv.w);
        #pragma unroll
        for (int off = 16; off; off >>= 1)
            s += __shfl_xor_sync(0xffffffffu, s, off);
        if (lane == 0) s_b2m = s * (1.0f / SD);
    }

    asm volatile("bar.sync 0, %0;" :: "n"(THREADS));

    // ---------------- phase 1: warp 12+r finishes row r ----------------
    const int r = warp - 12;
    const float* p = s_part + r * NH + lane;
    float v = ((p[0] + p[ROWS * NH]) + (p[2 * ROWS * NH] + p[3 * ROWS * NH]));
    v += fmaf(emb, w1e, b1v);

    float rsum = fmaxf(v, 0.0f) * s_w2m[lane];
    #pragma unroll
    for (int off = 16; off; off >>= 1)
        rsum += __shfl_xor_sync(0xffffffffu, rsum, off);

    const float m  = rsum + s_b2m;
    const float sp = fmaxf(m, 0.0f) + log1pf(__expf(-fabsf(m)));  // stable softplus

    const float4 av = reinterpret_cast<const float4*>(s_amp)[lane];
    float4 o;
    o.x = av.x * sp; o.y = av.y * sp; o.z = av.z * sp; o.w = av.w * sp;
    reinterpret_cast<float4*>(out + (b0 + r) * SD)[lane] = o;
}

extern "C" void kernel_launch(void* const* d_in, const int* in_sizes, int n_in,
                              void* d_out, int out_size)
{
    const float* x       = (const float*)d_in[0];
    const float* t       = (const float*)d_in[1];
    const float* log_amp = (const float*)d_in[2];
    const float* W1      = (const float*)d_in[3];
    const float* b1      = (const float*)d_in[4];
    const float* W2      = (const float*)d_in[5];
    const float* b2      = (const float*)d_in[6];
    float* out           = (float*)d_out;

    gnm_kernel<<<BATCH / ROWS, THREADS>>>(x, t, log_amp, W1, b1, W2, b2, out);
}

// round 7
// speedup vs baseline: 1.0386x; 1.0386x over previous
#include <cuda_runtime.h>
#include <cuda_bf16.h>
#include <math.h>

// Problem constants
#define SD 128      // STATE_DIM
#define NH 32       // HIDDEN
#define BATCH 512
#define ROWS 4      // batch rows per block
#define THREADS 384 // 12 warps, role-partitioned

// Math identity (verified R1-R6, rel_err ~9e-8):
//   out[b,n] = exp(log_amp[n,month]) *
//     softplus( sum_h relu(x[b]@W1 + emb*W1[128,:] + b1)[h] * mean_n W2[h,n] + mean(b2) )
//
// Warp roles (one __syncthreads total):
//   warps 0-3 : matvec; warp c = input chunk c for ALL 4 rows (W1 read once)
//   warps 4-7 : W2 row-means (8 rows each, coalesced float4)
//   warps 8-11: amp entry per thread + consumer/finisher for row (warp-8);
//               warp 8 also b2 mean; b1/W1-emb/emb prefetched pre-barrier

__global__ __launch_bounds__(THREADS, 1) void gnm_kernel(
    const float* __restrict__ x,        // [512,128]
    const float* __restrict__ t,        // [1]
    const float* __restrict__ log_amp,  // [128,12]
    const float* __restrict__ W1,       // [129,32]
    const float* __restrict__ b1,       // [32]
    const float* __restrict__ W2,       // [32,128]
    const float* __restrict__ b2,       // [128]
    float* __restrict__ out)            // [512,128]
{
    __shared__ float  s_part[4 * ROWS * NH];   // [chunk][row][h]
    __shared__ float  s_w2m[NH];               // W2 row means
    __shared__ float  s_amp[SD];
    __shared__ float  s_b2m;
    __shared__ float4 s_xt[4][NH];             // [chunk][j] = (x_row0..x_row3)[j]

    const int tid  = threadIdx.x;
    const int lane = tid & 31;
    const int warp = tid >> 5;
    const int b0   = blockIdx.x * ROWS;

    const float tv = t[0];

    if (warp < 4) {
        // ---------------- matvec: warp c handles chunk c for all 4 rows ----------------
        const int c = warp;
        const float xv0 = x[(b0 + 0) * SD + c * 32 + lane];
        const float xv1 = x[(b0 + 1) * SD + c * 32 + lane];
        const float xv2 = x[(b0 + 2) * SD + c * 32 + lane];
        const float xv3 = x[(b0 + 3) * SD + c * 32 + lane];
        s_xt[c][lane] = make_float4(xv0, xv1, xv2, xv3);   // conflict-free STS.128
        __syncwarp();

        const float* __restrict__ w1p = W1 + (c * 32) * NH + lane;
        float p0a = 0.f, p1a = 0.f, p2a = 0.f, p3a = 0.f;
        float p0b = 0.f, p1b = 0.f, p2b = 0.f, p3b = 0.f;
        #pragma unroll
        for (int j = 0; j < 32; j += 2) {
            const float  w0 = w1p[(j + 0) * NH];   // coalesced LDG, shared by 4 rows
            const float  w1 = w1p[(j + 1) * NH];
            const float4 xa = s_xt[c][j + 0];      // LDS.128 broadcast
            const float4 xb = s_xt[c][j + 1];
            p0a = fmaf(xa.x, w0, p0a); p1a = fmaf(xa.y, w0, p1a);
            p2a = fmaf(xa.z, w0, p2a); p3a = fmaf(xa.w, w0, p3a);
            p0b = fmaf(xb.x, w1, p0b); p1b = fmaf(xb.y, w1, p1b);
            p2b = fmaf(xb.z, w1, p2b); p3b = fmaf(xb.w, w1, p3b);
        }
        s_part[c * (ROWS * NH) + 0 * NH + lane] = p0a + p0b;
        s_part[c * (ROWS * NH) + 1 * NH + lane] = p1a + p1b;
        s_part[c * (ROWS * NH) + 2 * NH + lane] = p2a + p2b;
        s_part[c * (ROWS * NH) + 3 * NH + lane] = p3a + p3b;
    } else if (warp < 8) {
        // ---------------- W2 row means: warp g, rows g*8 .. g*8+7 ----------------
        const int g = warp - 4;
        #pragma unroll
        for (int i = 0; i < 8; i++) {
            const int   r = g * 8 + i;
            const float4 v = reinterpret_cast<const float4*>(W2 + r * SD)[lane];
            float s = (v.x + v.y) + (v.z + v.w);
            #pragma unroll
            for (int off = 16; off; off >>= 1)
                s += __shfl_xor_sync(0xffffffffu, s, off);
            if (lane == 0) s_w2m[r] = s * (1.0f / SD);
        }
    }

    // ---------------- consumers (warps 8-11): amp + prefetch pre-barrier ----------------
    float b1v = 0.f, w1e = 0.f, emb = 0.f;
    if (warp >= 8) {
        // amp entry for n = tid - 256 (0..127)
        const int n = tid - 256;
        const float4* lar = reinterpret_cast<const float4*>(log_amp + n * 12);
        const float4 la0 = lar[0], la1 = lar[1], la2 = lar[2];
        const float tm = (tv >= 12.0f) ? (tv - 12.0f) : tv;   // t in [0,24)
        const int month = (int)tm;
        float la = la0.x;
        la = (month ==  1) ? la0.y : la;
        la = (month ==  2) ? la0.z : la;
        la = (month ==  3) ? la0.w : la;
        la = (month ==  4) ? la1.x : la;
        la = (month ==  5) ? la1.y : la;
        la = (month ==  6) ? la1.z : la;
        la = (month ==  7) ? la1.w : la;
        la = (month ==  8) ? la2.x : la;
        la = (month ==  9) ? la2.y : la;
        la = (month == 10) ? la2.z : la;
        la = (month == 11) ? la2.w : la;
        s_amp[n] = __expf(la);

        b1v = b1[lane];
        w1e = W1[SD * NH + lane];
        emb = __sinf(0.5235987755982988f * tv);   // sin(2*pi*t/12)

        if (warp == 8) {
            const float4 bv = reinterpret_cast<const float4*>(b2)[lane];
            float s = (bv.x + bv.y) + (bv.z + bv.w);
            #pragma unroll
            for (int off = 16; off; off >>= 1)
                s += __shfl_xor_sync(0xffffffffu, s, off);
            if (lane == 0) s_b2m = s * (1.0f / SD);
        }
    }

    __syncthreads();

    // ---------------- phase 1: warp 8+r finishes row r ----------------
    if (warp >= 8) {
        const int r = warp - 8;
        const float* p = s_part + r * NH + lane;
        float v = ((p[0] + p[ROWS * NH]) + (p[2 * ROWS * NH] + p[3 * ROWS * NH]));
        v += fmaf(emb, w1e, b1v);

        float rsum = fmaxf(v, 0.0f) * s_w2m[lane];
        #pragma unroll
        for (int off = 16; off; off >>= 1)
            rsum += __shfl_xor_sync(0xffffffffu, rsum, off);

        const float m  = rsum + s_b2m;
        const float sp = fmaxf(m, 0.0f) + log1pf(__expf(-fabsf(m)));  // stable softplus

        const float4 av = reinterpret_cast<const float4*>(s_amp)[lane];
        float4 o;
        o.x = av.x * sp; o.y = av.y * sp; o.z = av.z * sp; o.w = av.w * sp;
        reinterpret_cast<float4*>(out + (b0 + r) * SD)[lane] = o;
    }
}

extern "C" void kernel_launch(void* const* d_in, const int* in_sizes, int n_in,
                              void* d_out, int out_size)
{
    const float* x       = (const float*)d_in[0];
    const float* t       = (const float*)d_in[1];
    const float* log_amp = (const float*)d_in[2];
    const float* W1      = (const float*)d_in[3];
    const float* b1      = (const float*)d_in[4];
    const float* W2      = (const float*)d_in[5];
    const float* b2      = (const float*)d_in[6];
    float* out           = (float*)d_out;

    gnm_kernel<<<BATCH / ROWS, THREADS>>>(x, t, log_amp, W1, b1, W2, b2, out);
}